// round 1
// baseline (speedup 1.0000x reference)
#include <cuda_runtime.h>

#define NNODES 50000
#define NEDGES 640000
#define HID    128
#define CLS    64

// ---------------- scratch (static __device__, no allocation) ----------------
__device__ float g_bufA[NNODES * HID];
__device__ float g_bufB[NNODES * HID];
__device__ float g_dinv[NNODES];
__device__ int   g_cnt[NNODES];
__device__ int   g_rowptr[NNODES + 1];
__device__ int   g_pos[NNODES];
__device__ int   g_srow[NEDGES];
__device__ float g_sdinv[NEDGES];   // dinv[row] aligned with g_srow

// ---------------- preprocessing ----------------
__global__ void k_clear_cnt() {
    int i = blockIdx.x * blockDim.x + threadIdx.x;
    if (i < NNODES) g_cnt[i] = 0;
}

__global__ void k_count(const int* __restrict__ col) {
    int e = blockIdx.x * blockDim.x + threadIdx.x;
    if (e < NEDGES) atomicAdd(&g_cnt[col[e]], 1);
}

__global__ void k_dinv() {
    int i = blockIdx.x * blockDim.x + threadIdx.x;
    if (i < NNODES) g_dinv[i] = rsqrtf((float)g_cnt[i] + 1.0f);
}

// Single-block exclusive scan of g_cnt -> g_rowptr (and g_pos copy).
__global__ void k_scan() {
    __shared__ int warp_sums[32];
    __shared__ int s_carry;
    const int tid  = threadIdx.x;       // 1024 threads
    const int lane = tid & 31;
    const int wid  = tid >> 5;
    if (tid == 0) s_carry = 0;
    __syncthreads();

    for (int base = 0; base < NNODES; base += 1024) {
        int i = base + tid;
        int v = (i < NNODES) ? g_cnt[i] : 0;
        // inclusive warp scan
        int x = v;
        #pragma unroll
        for (int o = 1; o < 32; o <<= 1) {
            int y = __shfl_up_sync(0xffffffffu, x, o);
            if (lane >= o) x += y;
        }
        if (lane == 31) warp_sums[wid] = x;
        __syncthreads();
        if (wid == 0) {
            int s = warp_sums[lane];
            #pragma unroll
            for (int o = 1; o < 32; o <<= 1) {
                int y = __shfl_up_sync(0xffffffffu, s, o);
                if (lane >= o) s += y;
            }
            warp_sums[lane] = s;
        }
        __syncthreads();
        int carry = s_carry;
        int inc   = x + (wid > 0 ? warp_sums[wid - 1] : 0);  // block-inclusive
        int excl  = carry + inc - v;
        if (i < NNODES) { g_rowptr[i] = excl; g_pos[i] = excl; }
        int block_total = warp_sums[31];
        __syncthreads();
        if (tid == 0) s_carry = carry + block_total;
        __syncthreads();
    }
    if (tid == 0) g_rowptr[NNODES] = NEDGES;
}

__global__ void k_scatter(const int* __restrict__ row, const int* __restrict__ col) {
    int e = blockIdx.x * blockDim.x + threadIdx.x;
    if (e < NEDGES) {
        int c = col[e];
        int r = row[e];
        int p = atomicAdd(&g_pos[c], 1);
        g_srow[p]  = r;
        g_sdinv[p] = g_dinv[r];
    }
}

// ---------------- SGEMM: C[M,BN] = A[M,HID] @ W[HID,BN] (+ bias) ----------------
// BM=128, BK=16, TM=8; 256 threads; BN in {128, 64}, TN = BN/16.
template <int BN, int TN>
__global__ void k_gemm(const float* __restrict__ A,
                       const float* __restrict__ W,
                       const float* __restrict__ bias,   // nullptr -> no bias
                       float* __restrict__ C,
                       int M) {
    constexpr int BM = 128;
    constexpr int BK = 16;
    constexpr int TM = 8;
    __shared__ __align__(16) float As[BK][BM];
    __shared__ __align__(16) float Bs[BK][BN];

    const int tid = threadIdx.x;             // 0..255
    const int tx  = tid & 15;                // col group
    const int ty  = tid >> 4;                // row group
    const int rowBase = blockIdx.x * BM;

    float acc[TM][TN];
    #pragma unroll
    for (int i = 0; i < TM; i++)
        #pragma unroll
        for (int j = 0; j < TN; j++) acc[i][j] = 0.0f;

    for (int k0 = 0; k0 < HID; k0 += BK) {
        // --- load A tile (BM x BK), store transposed As[k][m] ---
        #pragma unroll
        for (int i = 0; i < 2; i++) {
            int idx = tid + i * 256;                 // 0..511 float4 id
            int r   = idx >> 2;                      // 0..127
            int c4  = (idx & 3) * 4;                 // 0,4,8,12
            float4 v = make_float4(0.f, 0.f, 0.f, 0.f);
            int gr = rowBase + r;
            if (gr < M)
                v = *reinterpret_cast<const float4*>(A + (size_t)gr * HID + k0 + c4);
            As[c4 + 0][r] = v.x;
            As[c4 + 1][r] = v.y;
            As[c4 + 2][r] = v.z;
            As[c4 + 3][r] = v.w;
        }
        // --- load B tile (BK x BN) ---
        constexpr int B4 = (BK * BN) / 4;            // float4 count
        #pragma unroll
        for (int i = 0; i < B4 / 256; i++) {
            int idx = tid + i * 256;
            int r   = idx / (BN / 4);
            int c4  = (idx % (BN / 4)) * 4;
            float4 v = *reinterpret_cast<const float4*>(W + (size_t)(k0 + r) * BN + c4);
            *reinterpret_cast<float4*>(&Bs[r][c4]) = v;
        }
        __syncthreads();

        #pragma unroll
        for (int k = 0; k < BK; k++) {
            float a[TM], b[TN];
            #pragma unroll
            for (int i = 0; i < TM; i += 4)
                *reinterpret_cast<float4*>(&a[i]) =
                    *reinterpret_cast<const float4*>(&As[k][ty * TM + i]);
            #pragma unroll
            for (int j = 0; j < TN; j += 4)
                *reinterpret_cast<float4*>(&b[j]) =
                    *reinterpret_cast<const float4*>(&Bs[k][tx * TN + j]);
            #pragma unroll
            for (int i = 0; i < TM; i++)
                #pragma unroll
                for (int j = 0; j < TN; j++)
                    acc[i][j] += a[i] * b[j];
        }
        __syncthreads();
    }

    float bv[TN];
    #pragma unroll
    for (int j = 0; j < TN; j++) bv[j] = bias ? bias[tx * TN + j] : 0.0f;

    #pragma unroll
    for (int i = 0; i < TM; i++) {
        int gr = rowBase + ty * TM + i;
        if (gr < M) {
            #pragma unroll
            for (int j = 0; j < TN; j += 4) {
                float4 v = make_float4(acc[i][j] + bv[j],
                                       acc[i][j + 1] + bv[j + 1],
                                       acc[i][j + 2] + bv[j + 2],
                                       acc[i][j + 3] + bv[j + 3]);
                *reinterpret_cast<float4*>(C + (size_t)gr * BN + tx * TN + j) = v;
            }
        }
    }
}

// ---------------- neighbor aggregation (+self loop, +bias, ReLU) ----------------
// one warp per node; lane handles 4 contiguous features (float4)
__global__ void k_agg(const float* __restrict__ h,
                      const float* __restrict__ bias,
                      float* __restrict__ out) {
    int gwarp = (blockIdx.x * blockDim.x + threadIdx.x) >> 5;
    int lane  = threadIdx.x & 31;
    if (gwarp >= NNODES) return;
    const int n = gwarp;

    const float dn = g_dinv[n];
    float4 acc = *reinterpret_cast<const float4*>(h + (size_t)n * HID + lane * 4);
    const float sn = dn * dn;
    acc.x *= sn; acc.y *= sn; acc.z *= sn; acc.w *= sn;

    const int beg = g_rowptr[n];
    const int end = g_rowptr[n + 1];

    int e = beg;
    int   r_next = (e < end) ? g_srow[e]  : 0;
    float d_next = (e < end) ? g_sdinv[e] : 0.0f;
    while (e < end) {
        int   r  = r_next;
        float dr = d_next;
        ++e;
        if (e < end) { r_next = g_srow[e]; d_next = g_sdinv[e]; }
        float w = dr * dn;
        float4 hv = *reinterpret_cast<const float4*>(h + (size_t)r * HID + lane * 4);
        acc.x += hv.x * w;
        acc.y += hv.y * w;
        acc.z += hv.z * w;
        acc.w += hv.w * w;
    }

    float4 b = *reinterpret_cast<const float4*>(bias + lane * 4);
    acc.x = fmaxf(acc.x + b.x, 0.0f);
    acc.y = fmaxf(acc.y + b.y, 0.0f);
    acc.z = fmaxf(acc.z + b.z, 0.0f);
    acc.w = fmaxf(acc.w + b.w, 0.0f);
    *reinterpret_cast<float4*>(out + (size_t)n * HID + lane * 4) = acc;
}

// ---------------- launch ----------------
extern "C" void kernel_launch(void* const* d_in, const int* in_sizes, int n_in,
                              void* d_out, int out_size) {
    const float* x    = (const float*)d_in[0];
    const int*   ei   = (const int*)d_in[1];
    const int*   row  = ei;
    const int*   col  = ei + NEDGES;
    const float* W0   = (const float*)d_in[2];
    const float* b0   = (const float*)d_in[3];
    const float* W1   = (const float*)d_in[4];
    const float* b1   = (const float*)d_in[5];
    const float* W2   = (const float*)d_in[6];
    const float* b2   = (const float*)d_in[7];
    const float* Wlin = (const float*)d_in[8];
    const float* blin = (const float*)d_in[9];
    float* out = (float*)d_out;

    float *bufA, *bufB;
    cudaGetSymbolAddress((void**)&bufA, g_bufA);
    cudaGetSymbolAddress((void**)&bufB, g_bufB);

    // preprocessing (per launch; graph is input-dependent)
    k_clear_cnt<<<(NNODES + 255) / 256, 256>>>();
    k_count<<<(NEDGES + 255) / 256, 256>>>(col);
    k_dinv<<<(NNODES + 255) / 256, 256>>>();
    k_scan<<<1, 1024>>>();
    k_scatter<<<(NEDGES + 255) / 256, 256>>>(row, col);

    const int gemm_blocks = (NNODES + 127) / 128;
    const int agg_blocks  = (NNODES * 32 + 255) / 256;

    // layer 0
    k_gemm<128, 8><<<gemm_blocks, 256>>>(x, W0, nullptr, bufA, NNODES);
    k_agg<<<agg_blocks, 256>>>(bufA, b0, bufB);
    // layer 1
    k_gemm<128, 8><<<gemm_blocks, 256>>>(bufB, W1, nullptr, bufA, NNODES);
    k_agg<<<agg_blocks, 256>>>(bufA, b1, bufB);
    // layer 2
    k_gemm<128, 8><<<gemm_blocks, 256>>>(bufB, W2, nullptr, bufA, NNODES);
    k_agg<<<agg_blocks, 256>>>(bufA, b2, bufB);
    // output head
    k_gemm<64, 4><<<gemm_blocks, 256>>>(bufB, Wlin, blin, out, NNODES);
}